// round 13
// baseline (speedup 1.0000x reference)
#include <cuda_runtime.h>
#include <math.h>
#include <float.h>

// Fixed problem shape: img (16,3,512,512) f32, sbin=4 -> out (16,31,128,128) f32
#define BATCH 16
#define NCH   3
#define IH    512
#define IW    512
#define BH    128
#define BW    128

#define TS     16         // cells per tile side
#define WROWS  68         // pixel rows in window
#define MP     72         // smem pitch (u32): 16B-aligned strip stores
#define NSTRIP 18         // 4-px strips per row

#define NCHUNK 4          // pipeline chunks
#define BPC    (BATCH / NCHUNK)   // 4 batches per chunk

#define HIST_ELEMS (BATCH * 18 * BH * BW)
#define NORM_ELEMS (BATCH * BH * BW)

__device__ float g_hist[HIST_ELEMS];
__device__ float g_norm[NORM_ELEMS];

// ---------------------------------------------------------------------------
// Kernel 1 (identical to R10 best, + batch offset): gradients + orientation +
// per-cell gather + norm. One block = 16x16 cells of one batch image.
// ---------------------------------------------------------------------------
__global__ __launch_bounds__(256, 3) void hog_gather(const float* __restrict__ img,
                                                     int b0) {
    __shared__ unsigned int s_pack[WROWS * MP];   // 19584 B
    __shared__ float        s_bins[18 * 256];     // 18432 B  (total 38016 B)

    const int tid = threadIdx.x;
    const int cx0 = blockIdx.x * TS;
    const int cy0 = blockIdx.y * TS;
    const int b   = b0 + blockIdx.z;

    const int y0  = 4 * cy0 - 2;        // image row of window row 0
    const int x0a = 4 * cx0 - 4;        // image col of smem col 0 (aligned)

    const float* base = img + (size_t)b * NCH * IH * IW;

    const float UU[9] = {1.0f, 0.9397f, 0.766f, 0.5f, 0.1736f,
                         -0.1736f, -0.5f, -0.766f, -0.9397f};
    const float VV[9] = {0.0f, 0.342f, 0.6428f, 0.866f, 0.9848f,
                         0.9848f, 0.866f, 0.6428f, 0.342f};

    // ---- zero per-thread bins (owner-only; sync below covers it) ----
#pragma unroll
    for (int o = 0; o < 18; o++) s_bins[o * 256 + tid] = 0.0f;

    // ---- Stage 1: per-pixel gradient / orientation, 4-px aligned strips ----
    for (int t = tid; t < NSTRIP * WROWS; t += 256) {
        const int s  = t % NSTRIP;
        const int py = t / NSTRIP;
        const int y  = y0 + py;
        const int xb = x0a + 4 * s;

        uint4 pk = make_uint4(0u, 0u, 0u, 0u);

        if (y >= 1 && y <= IH - 2 && xb >= 0 && xb <= IW - 4) {
            float bestv[4] = {-1.f, -1.f, -1.f, -1.f};
            float bdx[4], bdy[4];
#pragma unroll
            for (int c = 0; c < NCH; c++) {
                const float* rp = base + (size_t)c * IH * IW + (size_t)y * IW + xb;
                float4 up = *reinterpret_cast<const float4*>(rp - IW);
                float4 dn = *reinterpret_cast<const float4*>(rp + IW);
                float4 md = *reinterpret_cast<const float4*>(rp);
                float  lf = (xb > 0) ? rp[-1] : 0.f;
                float  rt = (xb + 4 <= IW - 1) ? rp[4] : 0.f;
                float mx[6] = {lf, md.x, md.y, md.z, md.w, rt};
                float u[4]  = {up.x, up.y, up.z, up.w};
                float d[4]  = {dn.x, dn.y, dn.z, dn.w};
#pragma unroll
                for (int i = 0; i < 4; i++) {
                    float gdy = d[i] - u[i];
                    float gdx = mx[i + 2] - mx[i];
                    float v = gdx * gdx + gdy * gdy;
                    if (v > bestv[i]) { bestv[i] = v; bdx[i] = gdx; bdy[i] = gdy; }
                }
            }
            unsigned int pka[4];
#pragma unroll
            for (int i = 0; i < 4; i++) {
                const float gdx = bdx[i];
                const float gdy = bdy[i];

                float d[9];
#pragma unroll
                for (int k = 0; k < 9; k++) d[k] = UU[k] * gdx + VV[k] * gdy;

                float mx01 = fmaxf(d[0], d[1]), mx23 = fmaxf(d[2], d[3]);
                float mx45 = fmaxf(d[4], d[5]), mx67 = fmaxf(d[6], d[7]);
                float mxv = fmaxf(fmaxf(fmaxf(mx01, mx23), fmaxf(mx45, mx67)), d[8]);
                float mn01 = fminf(d[0], d[1]), mn23 = fminf(d[2], d[3]);
                float mn45 = fminf(d[4], d[5]), mn67 = fminf(d[6], d[7]);
                float mnv = fminf(fminf(fminf(mn01, mn23), fminf(mn45, mn67)), d[8]);

                bool pos = (mxv >= -mnv);           // positives first on tie
                float tgt = pos ? mxv : mnv;

                unsigned int mask = 0u;
#pragma unroll
                for (int k = 0; k < 9; k++)
                    mask |= (d[k] == tgt) ? (1u << k) : 0u;
                int kk = __ffs(mask) - 1;            // first occurrence
                int bo = pos ? kk : kk + 9;

                float vm = bestv[i];
                float mag = (vm > 0.f) ? vm * rsqrtf(vm) : 0.f;
                int x = xb + i;
                if (x < 1 || x > IW - 2) mag = 0.f;
                pka[i] = (__float_as_uint(mag) & 0xFFFFFFE0u) | (unsigned)bo;
            }
            pk = make_uint4(pka[0], pka[1], pka[2], pka[3]);
        }
        *reinterpret_cast<uint4*>(&s_pack[py * MP + 4 * s]) = pk;
    }

    __syncthreads();

    // ---- Stage 3: gather 8x8 footprint per cell (1 thread = 1 cell) ----
    const int lcy = tid >> 4;
    const int lcx = tid & 15;
    const int pr  = 4 * lcy;
    const int pc  = 4 * lcx;

    const float W8[8] = {0.125f, 0.375f, 0.625f, 0.875f,
                         0.875f, 0.625f, 0.375f, 0.125f};

#pragma unroll
    for (int dy = 0; dy < 8; dy++) {
        const float wy = W8[dy];
        const unsigned int* rowp = &s_pack[(pr + dy) * MP + pc];
        uint4 p0 = *reinterpret_cast<const uint4*>(rowp);
        uint4 p1 = *reinterpret_cast<const uint4*>(rowp + 4);
        uint4 p2 = *reinterpret_cast<const uint4*>(rowp + 8);
        unsigned int v[12] = {p0.x, p0.y, p0.z, p0.w,
                              p1.x, p1.y, p1.z, p1.w,
                              p2.x, p2.y, p2.z, p2.w};
#pragma unroll
        for (int dx = 0; dx < 8; dx++) {
            unsigned int u = v[dx + 2];
            float m = __uint_as_float(u & 0xFFFFFFE0u);
            int o = (int)(u & 31u);
            s_bins[o * 256 + tid] += m * (wy * W8[dx]);
        }
    }

    // ---- Stage 4: write hist + norm (coalesced stores) ----
    const int cy = cy0 + lcy;
    const int cx = cx0 + lcx;
    float* hb = g_hist + ((size_t)b * 18) * (BH * BW) + cy * BW + cx;

    float acc = 0.0f;
#pragma unroll
    for (int o = 0; o < 9; o++) {
        float a = s_bins[o * 256 + tid];
        float c = s_bins[(o + 9) * 256 + tid];
        hb[o * (BH * BW)]       = a;
        hb[(o + 9) * (BH * BW)] = c;
        float s = a + c;
        acc += s * s;
    }
    g_norm[(size_t)b * BH * BW + cy * BW + cx] = acc;
}

// ---------------------------------------------------------------------------
// Kernel 2 (identical to R10 best, + batch offset): features, 1 px/thread.
// ---------------------------------------------------------------------------
__global__ __launch_bounds__(256) void hog_feat(float* __restrict__ out, int b0) {
    int idx = blockIdx.x * blockDim.x + threadIdx.x;
    if (idx >= BPC * BH * BW) return;
    int j = idx & (BW - 1);
    int t = idx >> 7;
    int i = t & (BH - 1);
    int b = b0 + (t >> 7);

    float* ob = out + (size_t)b * 31 * BH * BW + i * BW + j;

    if (i == 0 || i == BH - 1 || j == 0 || j == BW - 1) {
#pragma unroll
        for (int ch = 0; ch < 31; ch++) ob[ch * (BH * BW)] = 0.0f;
        return;
    }

    const float* hb = g_hist + (size_t)b * 18 * BH * BW + i * BW + j;
    float src[18];
#pragma unroll
    for (int o = 0; o < 18; o++) src[o] = hb[o * (BH * BW)];

    const float* nb = g_norm + (size_t)b * BH * BW;
    float m[3][3];
#pragma unroll
    for (int r = 0; r < 3; r++)
#pragma unroll
        for (int c = 0; c < 3; c++)
            m[r][c] = nb[(i - 1 + r) * BW + (j - 1 + c)];

    const float EPS = 0.0001f;
    float n1 = rsqrtf(m[1][1] + m[2][1] + m[1][2] + m[2][2] + EPS);
    float n2 = rsqrtf(m[0][1] + m[1][1] + m[0][2] + m[1][2] + EPS);
    float n3 = rsqrtf(m[1][0] + m[2][0] + m[1][1] + m[2][1] + EPS);
    float n4 = rsqrtf(m[0][0] + m[1][0] + m[0][1] + m[1][1] + EPS);

    float t1 = 0.f, t2 = 0.f, t3 = 0.f, t4 = 0.f;
#pragma unroll
    for (int o = 0; o < 9; o++) {
        float a = src[o];
        float c = src[o + 9];

        float a1 = fminf(a * n1, 0.2f);
        float a2 = fminf(a * n2, 0.2f);
        float a3 = fminf(a * n3, 0.2f);
        float a4 = fminf(a * n4, 0.2f);
        float c1 = fminf(c * n1, 0.2f);
        float c2 = fminf(c * n2, 0.2f);
        float c3 = fminf(c * n3, 0.2f);
        float c4 = fminf(c * n4, 0.2f);

        ob[o * (BH * BW)]       = 0.5f * (a1 + a2 + a3 + a4);
        ob[(o + 9) * (BH * BW)] = 0.5f * (c1 + c2 + c3 + c4);

        float ss = a + c;
        float v = fminf(ss * n1, 0.2f) + fminf(ss * n2, 0.2f) +
                  fminf(ss * n3, 0.2f) + fminf(ss * n4, 0.2f);
        ob[(18 + o) * (BH * BW)] = 0.5f * v;

        t1 += a1 + c1;
        t2 += a2 + c2;
        t3 += a3 + c3;
        t4 += a4 + c4;
    }
    ob[27 * (BH * BW)] = 0.2357f * t1;
    ob[28 * (BH * BW)] = 0.2357f * t2;
    ob[29 * (BH * BW)] = 0.2357f * t3;
    ob[30 * (BH * BW)] = 0.2357f * t4;
}

// ---------------------------------------------------------------------------
// Pipelined launch: gather chunks on the capture-origin stream; each feat
// chunk on a forked stream, gated by an event after its gather chunk, so
// feat(chunk i) overlaps gather(chunk i+1). Fork/join is capture-legal.
// Streams/events are host objects (no device memory); kernel_launch is only
// invoked a handful of times (correctness + capture), so not destroying them
// is a bounded host-side leak, and behavior is identical on every call.
// ---------------------------------------------------------------------------
extern "C" void kernel_launch(void* const* d_in, const int* in_sizes, int n_in,
                              void* d_out, int out_size) {
    const float* img = (const float*)d_in[0];
    float* out = (float*)d_out;

    cudaStream_t s2;
    cudaStreamCreateWithFlags(&s2, cudaStreamNonBlocking);

    dim3 ggrid(BW / TS, BH / TS, BPC);            // (8, 8, 4) per chunk
    const int fthreads = BPC * BH * BW;           // 65536 per chunk
    const int fblocks  = (fthreads + 255) / 256;  // 256 blocks

    cudaEvent_t ev;
    for (int c = 0; c < NCHUNK; c++) {
        const int b0 = c * BPC;
        hog_gather<<<ggrid, 256>>>(img, b0);              // stream 0 (origin)
        cudaEventCreateWithFlags(&ev, cudaEventDisableTiming);
        cudaEventRecord(ev, 0);
        cudaStreamWaitEvent(s2, ev, 0);
        hog_feat<<<fblocks, 256, 0, s2>>>(out, b0);       // overlapped stream
    }
    // join the forked stream back into the origin stream
    cudaEvent_t done;
    cudaEventCreateWithFlags(&done, cudaEventDisableTiming);
    cudaEventRecord(done, s2);
    cudaStreamWaitEvent(0, done, 0);
}

// round 14
// speedup vs baseline: 1.6720x; 1.6720x over previous
#include <cuda_runtime.h>
#include <math.h>
#include <float.h>

// Fixed problem shape: img (16,3,512,512) f32, sbin=4 -> out (16,31,128,128) f32
#define BATCH 16
#define NCH   3
#define IH    512
#define IW    512
#define BH    128
#define BW    128

#define TS     16         // cells per tile side
#define WROWS  68         // pixel rows in window
#define MP     72         // smem pitch (u32): 16B-aligned strip stores
#define NSTRIP 18         // 4-px strips per row

#define HIST_ELEMS (BATCH * 18 * BH * BW)
#define NORM_ELEMS (BATCH * BH * BW)

__device__ float g_hist[HIST_ELEMS];
__device__ float g_norm[NORM_ELEMS];

// ---------------------------------------------------------------------------
// Kernel 1: gradients + orientation + per-cell gather + norm (R10 base).
// Orientation via 9 adjacent-boundary sign tests (circular unimodal argmax):
//   T_k = (UU_k - UU_{k+1})*gdx + (VV_k - VV_{k+1})*gdy   (k = 0..7)
//   T_8 = (UU_8 + UU_0)*gdx + (VV_8 + VV_0)*gdy           (8|9 boundary)
//   B[0..17] = [T0..T8, ~T0..~T8];  bin = ffs(B & ~rot1(B)) - 1
// ---------------------------------------------------------------------------
__global__ __launch_bounds__(256, 3) void hog_gather(const float* __restrict__ img) {
    __shared__ unsigned int s_pack[WROWS * MP];   // 19584 B
    __shared__ float        s_bins[18 * 256];     // 18432 B  (total 38016 B)

    const int tid = threadIdx.x;
    const int cx0 = blockIdx.x * TS;
    const int cy0 = blockIdx.y * TS;
    const int b   = blockIdx.z;

    const int y0  = 4 * cy0 - 2;        // image row of window row 0
    const int x0a = 4 * cx0 - 4;        // image col of smem col 0 (aligned)

    const float* base = img + (size_t)b * NCH * IH * IW;

    // boundary-line normals, constant-folded in float from the UU/VV table
    const float C1[9] = {1.0f - 0.9397f,      0.9397f - 0.766f,
                         0.766f - 0.5f,       0.5f - 0.1736f,
                         0.1736f - (-0.1736f), (-0.1736f) - (-0.5f),
                         (-0.5f) - (-0.766f), (-0.766f) - (-0.9397f),
                         (-0.9397f) + 1.0f};
    const float C2[9] = {0.0f - 0.342f,       0.342f - 0.6428f,
                         0.6428f - 0.866f,    0.866f - 0.9848f,
                         0.9848f - 0.9848f,   0.9848f - 0.866f,
                         0.866f - 0.6428f,    0.6428f - 0.342f,
                         0.342f + 0.0f};

    // ---- zero per-thread bins (owner-only; sync below covers it) ----
#pragma unroll
    for (int o = 0; o < 18; o++) s_bins[o * 256 + tid] = 0.0f;

    // ---- Stage 1: per-pixel gradient / orientation, 4-px aligned strips ----
    for (int t = tid; t < NSTRIP * WROWS; t += 256) {
        const int s  = t % NSTRIP;
        const int py = t / NSTRIP;
        const int y  = y0 + py;
        const int xb = x0a + 4 * s;

        uint4 pk = make_uint4(0u, 0u, 0u, 0u);

        if (y >= 1 && y <= IH - 2 && xb >= 0 && xb <= IW - 4) {
            float bestv[4] = {-1.f, -1.f, -1.f, -1.f};
            float bdx[4], bdy[4];
#pragma unroll
            for (int c = 0; c < NCH; c++) {
                const float* rp = base + (size_t)c * IH * IW + (size_t)y * IW + xb;
                float4 up = *reinterpret_cast<const float4*>(rp - IW);
                float4 dn = *reinterpret_cast<const float4*>(rp + IW);
                float4 md = *reinterpret_cast<const float4*>(rp);
                float  lf = (xb > 0) ? rp[-1] : 0.f;
                float  rt = (xb + 4 <= IW - 1) ? rp[4] : 0.f;
                float mx[6] = {lf, md.x, md.y, md.z, md.w, rt};
                float u[4]  = {up.x, up.y, up.z, up.w};
                float d[4]  = {dn.x, dn.y, dn.z, dn.w};
#pragma unroll
                for (int i = 0; i < 4; i++) {
                    float gdy = d[i] - u[i];
                    float gdx = mx[i + 2] - mx[i];
                    float v = gdx * gdx + gdy * gdy;
                    if (v > bestv[i]) { bestv[i] = v; bdx[i] = gdx; bdy[i] = gdy; }
                }
            }
            unsigned int pka[4];
#pragma unroll
            for (int i = 0; i < 4; i++) {
                const float gdx = bdx[i];
                const float gdy = bdy[i];

                // 9 boundary sign tests -> 18-bit adjacency pattern
                unsigned int tmask = 0u;
#pragma unroll
                for (int k = 0; k < 9; k++) {
                    float T = C1[k] * gdx + C2[k] * gdy;
                    if (T >= 0.f) tmask |= (1u << k);
                }
                unsigned int full = tmask | ((~tmask & 0x1FFu) << 9);
                unsigned int prev = ((full << 1) | (full >> 17)) & 0x3FFFFu;
                unsigned int mbit = full & ~prev;     // unique max position
                int bo = __ffs(mbit) - 1;

                float vm = bestv[i];
                float mag = (vm > 0.f) ? vm * rsqrtf(vm) : 0.f;
                int x = xb + i;
                if (x < 1 || x > IW - 2) mag = 0.f;
                pka[i] = (__float_as_uint(mag) & 0xFFFFFFE0u) | (unsigned)bo;
            }
            pk = make_uint4(pka[0], pka[1], pka[2], pka[3]);
        }
        *reinterpret_cast<uint4*>(&s_pack[py * MP + 4 * s]) = pk;
    }

    __syncthreads();

    // ---- Stage 3: gather 8x8 footprint per cell (1 thread = 1 cell) ----
    const int lcy = tid >> 4;
    const int lcx = tid & 15;
    const int pr  = 4 * lcy;
    const int pc  = 4 * lcx;

    const float W8[8] = {0.125f, 0.375f, 0.625f, 0.875f,
                         0.875f, 0.625f, 0.375f, 0.125f};

#pragma unroll
    for (int dy = 0; dy < 8; dy++) {
        const float wy = W8[dy];
        const unsigned int* rowp = &s_pack[(pr + dy) * MP + pc];
        uint4 p0 = *reinterpret_cast<const uint4*>(rowp);
        uint4 p1 = *reinterpret_cast<const uint4*>(rowp + 4);
        uint4 p2 = *reinterpret_cast<const uint4*>(rowp + 8);
        unsigned int v[12] = {p0.x, p0.y, p0.z, p0.w,
                              p1.x, p1.y, p1.z, p1.w,
                              p2.x, p2.y, p2.z, p2.w};
#pragma unroll
        for (int dx = 0; dx < 8; dx++) {
            unsigned int u = v[dx + 2];
            float m = __uint_as_float(u & 0xFFFFFFE0u);
            int o = (int)(u & 31u);
            s_bins[o * 256 + tid] += m * (wy * W8[dx]);
        }
    }

    // ---- Stage 4: write hist + norm (coalesced stores) ----
    const int cy = cy0 + lcy;
    const int cx = cx0 + lcx;
    float* hb = g_hist + ((size_t)b * 18) * (BH * BW) + cy * BW + cx;

    float acc = 0.0f;
#pragma unroll
    for (int o = 0; o < 9; o++) {
        float a = s_bins[o * 256 + tid];
        float c = s_bins[(o + 9) * 256 + tid];
        hb[o * (BH * BW)]       = a;
        hb[(o + 9) * (BH * BW)] = c;
        float s = a + c;
        acc += s * s;
    }
    g_norm[(size_t)b * BH * BW + cy * BW + cx] = acc;
}

// ---------------------------------------------------------------------------
// Kernel 2: block-normalized features, 1 px/thread, fused o-loop (R10 best).
// ---------------------------------------------------------------------------
__global__ __launch_bounds__(256) void hog_feat(float* __restrict__ out) {
    int idx = blockIdx.x * blockDim.x + threadIdx.x;
    if (idx >= BATCH * BH * BW) return;
    int j = idx & (BW - 1);
    int t = idx >> 7;
    int i = t & (BH - 1);
    int b = t >> 7;

    float* ob = out + (size_t)b * 31 * BH * BW + i * BW + j;

    if (i == 0 || i == BH - 1 || j == 0 || j == BW - 1) {
#pragma unroll
        for (int ch = 0; ch < 31; ch++) ob[ch * (BH * BW)] = 0.0f;
        return;
    }

    const float* hb = g_hist + (size_t)b * 18 * BH * BW + i * BW + j;
    float src[18];
#pragma unroll
    for (int o = 0; o < 18; o++) src[o] = hb[o * (BH * BW)];

    const float* nb = g_norm + (size_t)b * BH * BW;
    float m[3][3];
#pragma unroll
    for (int r = 0; r < 3; r++)
#pragma unroll
        for (int c = 0; c < 3; c++)
            m[r][c] = nb[(i - 1 + r) * BW + (j - 1 + c)];

    const float EPS = 0.0001f;
    float n1 = rsqrtf(m[1][1] + m[2][1] + m[1][2] + m[2][2] + EPS);
    float n2 = rsqrtf(m[0][1] + m[1][1] + m[0][2] + m[1][2] + EPS);
    float n3 = rsqrtf(m[1][0] + m[2][0] + m[1][1] + m[2][1] + EPS);
    float n4 = rsqrtf(m[0][0] + m[1][0] + m[0][1] + m[1][1] + EPS);

    float t1 = 0.f, t2 = 0.f, t3 = 0.f, t4 = 0.f;
#pragma unroll
    for (int o = 0; o < 9; o++) {
        float a = src[o];
        float c = src[o + 9];

        float a1 = fminf(a * n1, 0.2f);
        float a2 = fminf(a * n2, 0.2f);
        float a3 = fminf(a * n3, 0.2f);
        float a4 = fminf(a * n4, 0.2f);
        float c1 = fminf(c * n1, 0.2f);
        float c2 = fminf(c * n2, 0.2f);
        float c3 = fminf(c * n3, 0.2f);
        float c4 = fminf(c * n4, 0.2f);

        ob[o * (BH * BW)]       = 0.5f * (a1 + a2 + a3 + a4);
        ob[(o + 9) * (BH * BW)] = 0.5f * (c1 + c2 + c3 + c4);

        float ss = a + c;
        float v = fminf(ss * n1, 0.2f) + fminf(ss * n2, 0.2f) +
                  fminf(ss * n3, 0.2f) + fminf(ss * n4, 0.2f);
        ob[(18 + o) * (BH * BW)] = 0.5f * v;

        t1 += a1 + c1;
        t2 += a2 + c2;
        t3 += a3 + c3;
        t4 += a4 + c4;
    }
    ob[27 * (BH * BW)] = 0.2357f * t1;
    ob[28 * (BH * BW)] = 0.2357f * t2;
    ob[29 * (BH * BW)] = 0.2357f * t3;
    ob[30 * (BH * BW)] = 0.2357f * t4;
}

// ---------------------------------------------------------------------------
extern "C" void kernel_launch(void* const* d_in, const int* in_sizes, int n_in,
                              void* d_out, int out_size) {
    const float* img = (const float*)d_in[0];
    float* out = (float*)d_out;

    dim3 grid(BW / TS, BH / TS, BATCH);   // (8, 8, 16)
    hog_gather<<<grid, 256>>>(img);

    int n = BATCH * BH * BW;
    hog_feat<<<(n + 255) / 256, 256>>>(out);
}

// round 15
// speedup vs baseline: 1.6823x; 1.0061x over previous
#include <cuda_runtime.h>
#include <math.h>
#include <float.h>

// Fixed problem shape: img (16,3,512,512) f32, sbin=4 -> out (16,31,128,128) f32
#define BATCH 16
#define NCH   3
#define IH    512
#define IW    512
#define BH    128
#define BW    128

#define TS     16         // cells per tile side
#define WROWS  68         // pixel rows in window
#define MP     72         // smem pitch (u32): 16B-aligned strip stores
#define NSTRIP 18         // 4-px strips per row

#define HIST_ELEMS (BATCH * 18 * BH * BW)
#define NORM_ELEMS (BATCH * BH * BW)

__device__ float g_hist[HIST_ELEMS];
__device__ float g_norm[NORM_ELEMS];

// ---------------------------------------------------------------------------
// Kernel 1: gradients + orientation + per-cell gather + norm.
// Orientation argmax over D = [d0..d8, -d0..-d8] via adjacency comparisons of
// the ACTUAL dots (decision-consistent with a true argmax):
//   full[j]   = (D_j >= D_{j+1})  built from 9 comparisons:
//     j<8 : d_j >= d_{j+1}
//     j=8 : d_8 >= -d_0
//     j>8 : complement of bit j-9
//   bin = ffs(full & ~rot1(full)) - 1   (first local max == first global max)
// ---------------------------------------------------------------------------
__global__ __launch_bounds__(256, 3) void hog_gather(const float* __restrict__ img) {
    __shared__ unsigned int s_pack[WROWS * MP];   // 19584 B
    __shared__ float        s_bins[18 * 256];     // 18432 B  (total 38016 B)

    const int tid = threadIdx.x;
    const int cx0 = blockIdx.x * TS;
    const int cy0 = blockIdx.y * TS;
    const int b   = blockIdx.z;

    const int y0  = 4 * cy0 - 2;        // image row of window row 0
    const int x0a = 4 * cx0 - 4;        // image col of smem col 0 (aligned)

    const float* base = img + (size_t)b * NCH * IH * IW;

    const float UU[9] = {1.0f, 0.9397f, 0.766f, 0.5f, 0.1736f,
                         -0.1736f, -0.5f, -0.766f, -0.9397f};
    const float VV[9] = {0.0f, 0.342f, 0.6428f, 0.866f, 0.9848f,
                         0.9848f, 0.866f, 0.6428f, 0.342f};

    // ---- zero per-thread bins (owner-only; sync below covers it) ----
#pragma unroll
    for (int o = 0; o < 18; o++) s_bins[o * 256 + tid] = 0.0f;

    // ---- Stage 1: per-pixel gradient / orientation, 4-px aligned strips ----
    for (int t = tid; t < NSTRIP * WROWS; t += 256) {
        const int s  = t % NSTRIP;
        const int py = t / NSTRIP;
        const int y  = y0 + py;
        const int xb = x0a + 4 * s;

        uint4 pk = make_uint4(0u, 0u, 0u, 0u);

        if (y >= 1 && y <= IH - 2 && xb >= 0 && xb <= IW - 4) {
            float bestv[4] = {-1.f, -1.f, -1.f, -1.f};
            float bdx[4], bdy[4];
#pragma unroll
            for (int c = 0; c < NCH; c++) {
                const float* rp = base + (size_t)c * IH * IW + (size_t)y * IW + xb;
                float4 up = *reinterpret_cast<const float4*>(rp - IW);
                float4 dn = *reinterpret_cast<const float4*>(rp + IW);
                float4 md = *reinterpret_cast<const float4*>(rp);
                float  lf = (xb > 0) ? rp[-1] : 0.f;
                float  rt = (xb + 4 <= IW - 1) ? rp[4] : 0.f;
                float mx[6] = {lf, md.x, md.y, md.z, md.w, rt};
                float u[4]  = {up.x, up.y, up.z, up.w};
                float d[4]  = {dn.x, dn.y, dn.z, dn.w};
#pragma unroll
                for (int i = 0; i < 4; i++) {
                    float gdy = d[i] - u[i];
                    float gdx = mx[i + 2] - mx[i];
                    float v = gdx * gdx + gdy * gdy;
                    if (v > bestv[i]) { bestv[i] = v; bdx[i] = gdx; bdy[i] = gdy; }
                }
            }
            unsigned int pka[4];
#pragma unroll
            for (int i = 0; i < 4; i++) {
                const float gdx = bdx[i];
                const float gdy = bdy[i];

                // the 9 dots, computed once; all decisions compare THESE values
                float d[9];
#pragma unroll
                for (int k = 0; k < 9; k++) d[k] = UU[k] * gdx + VV[k] * gdy;

                unsigned int tmask = 0u;
#pragma unroll
                for (int k = 0; k < 8; k++)
                    if (d[k] >= d[k + 1]) tmask |= (1u << k);
                if (d[8] >= -d[0]) tmask |= (1u << 8);

                unsigned int full = tmask | ((~tmask & 0x1FFu) << 9);
                unsigned int prev = ((full << 1) | (full >> 17)) & 0x3FFFFu;
                unsigned int mbit = full & ~prev;     // local-max positions
                int bo = __ffs(mbit) - 1;

                float vm = bestv[i];
                float mag = (vm > 0.f) ? vm * rsqrtf(vm) : 0.f;
                int x = xb + i;
                if (x < 1 || x > IW - 2) mag = 0.f;
                pka[i] = (__float_as_uint(mag) & 0xFFFFFFE0u) | (unsigned)bo;
            }
            pk = make_uint4(pka[0], pka[1], pka[2], pka[3]);
        }
        *reinterpret_cast<uint4*>(&s_pack[py * MP + 4 * s]) = pk;
    }

    __syncthreads();

    // ---- Stage 3: gather 8x8 footprint per cell (1 thread = 1 cell) ----
    const int lcy = tid >> 4;
    const int lcx = tid & 15;
    const int pr  = 4 * lcy;
    const int pc  = 4 * lcx;

    const float W8[8] = {0.125f, 0.375f, 0.625f, 0.875f,
                         0.875f, 0.625f, 0.375f, 0.125f};

#pragma unroll
    for (int dy = 0; dy < 8; dy++) {
        const float wy = W8[dy];
        const unsigned int* rowp = &s_pack[(pr + dy) * MP + pc];
        uint4 p0 = *reinterpret_cast<const uint4*>(rowp);
        uint4 p1 = *reinterpret_cast<const uint4*>(rowp + 4);
        uint4 p2 = *reinterpret_cast<const uint4*>(rowp + 8);
        unsigned int v[12] = {p0.x, p0.y, p0.z, p0.w,
                              p1.x, p1.y, p1.z, p1.w,
                              p2.x, p2.y, p2.z, p2.w};
#pragma unroll
        for (int dx = 0; dx < 8; dx++) {
            unsigned int u = v[dx + 2];
            float m = __uint_as_float(u & 0xFFFFFFE0u);
            int o = (int)(u & 31u);
            s_bins[o * 256 + tid] += m * (wy * W8[dx]);
        }
    }

    // ---- Stage 4: write hist + norm (coalesced stores) ----
    const int cy = cy0 + lcy;
    const int cx = cx0 + lcx;
    float* hb = g_hist + ((size_t)b * 18) * (BH * BW) + cy * BW + cx;

    float acc = 0.0f;
#pragma unroll
    for (int o = 0; o < 9; o++) {
        float a = s_bins[o * 256 + tid];
        float c = s_bins[(o + 9) * 256 + tid];
        hb[o * (BH * BW)]       = a;
        hb[(o + 9) * (BH * BW)] = c;
        float s = a + c;
        acc += s * s;
    }
    g_norm[(size_t)b * BH * BW + cy * BW + cx] = acc;
}

// ---------------------------------------------------------------------------
// Kernel 2: block-normalized features, 1 px/thread, fused o-loop (R10 best).
// ---------------------------------------------------------------------------
__global__ __launch_bounds__(256) void hog_feat(float* __restrict__ out) {
    int idx = blockIdx.x * blockDim.x + threadIdx.x;
    if (idx >= BATCH * BH * BW) return;
    int j = idx & (BW - 1);
    int t = idx >> 7;
    int i = t & (BH - 1);
    int b = t >> 7;

    float* ob = out + (size_t)b * 31 * BH * BW + i * BW + j;

    if (i == 0 || i == BH - 1 || j == 0 || j == BW - 1) {
#pragma unroll
        for (int ch = 0; ch < 31; ch++) ob[ch * (BH * BW)] = 0.0f;
        return;
    }

    const float* hb = g_hist + (size_t)b * 18 * BH * BW + i * BW + j;
    float src[18];
#pragma unroll
    for (int o = 0; o < 18; o++) src[o] = hb[o * (BH * BW)];

    const float* nb = g_norm + (size_t)b * BH * BW;
    float m[3][3];
#pragma unroll
    for (int r = 0; r < 3; r++)
#pragma unroll
        for (int c = 0; c < 3; c++)
            m[r][c] = nb[(i - 1 + r) * BW + (j - 1 + c)];

    const float EPS = 0.0001f;
    float n1 = rsqrtf(m[1][1] + m[2][1] + m[1][2] + m[2][2] + EPS);
    float n2 = rsqrtf(m[0][1] + m[1][1] + m[0][2] + m[1][2] + EPS);
    float n3 = rsqrtf(m[1][0] + m[2][0] + m[1][1] + m[2][1] + EPS);
    float n4 = rsqrtf(m[0][0] + m[1][0] + m[0][1] + m[1][1] + EPS);

    float t1 = 0.f, t2 = 0.f, t3 = 0.f, t4 = 0.f;
#pragma unroll
    for (int o = 0; o < 9; o++) {
        float a = src[o];
        float c = src[o + 9];

        float a1 = fminf(a * n1, 0.2f);
        float a2 = fminf(a * n2, 0.2f);
        float a3 = fminf(a * n3, 0.2f);
        float a4 = fminf(a * n4, 0.2f);
        float c1 = fminf(c * n1, 0.2f);
        float c2 = fminf(c * n2, 0.2f);
        float c3 = fminf(c * n3, 0.2f);
        float c4 = fminf(c * n4, 0.2f);

        ob[o * (BH * BW)]       = 0.5f * (a1 + a2 + a3 + a4);
        ob[(o + 9) * (BH * BW)] = 0.5f * (c1 + c2 + c3 + c4);

        float ss = a + c;
        float v = fminf(ss * n1, 0.2f) + fminf(ss * n2, 0.2f) +
                  fminf(ss * n3, 0.2f) + fminf(ss * n4, 0.2f);
        ob[(18 + o) * (BH * BW)] = 0.5f * v;

        t1 += a1 + c1;
        t2 += a2 + c2;
        t3 += a3 + c3;
        t4 += a4 + c4;
    }
    ob[27 * (BH * BW)] = 0.2357f * t1;
    ob[28 * (BH * BW)] = 0.2357f * t2;
    ob[29 * (BH * BW)] = 0.2357f * t3;
    ob[30 * (BH * BW)] = 0.2357f * t4;
}

// ---------------------------------------------------------------------------
extern "C" void kernel_launch(void* const* d_in, const int* in_sizes, int n_in,
                              void* d_out, int out_size) {
    const float* img = (const float*)d_in[0];
    float* out = (float*)d_out;

    dim3 grid(BW / TS, BH / TS, BATCH);   // (8, 8, 16)
    hog_gather<<<grid, 256>>>(img);

    int n = BATCH * BH * BW;
    hog_feat<<<(n + 255) / 256, 256>>>(out);
}